// round 12
// baseline (speedup 1.0000x reference)
#include <cuda_runtime.h>
#include <cstdint>

// ---------------- problem constants ----------------
#define C_CORES 64
#define D_EMB   128
#define CD      (C_CORES * D_EMB)      // 8192
#define TPB     512                    // 16 warps: warp w owns cores 4w..4w+3
#define NW      (TPB / 32)
#define CPW     4                      // cores per warp
#define CAP     256                    // per-core local bin capacity (mean ~21)
#define BD      8                      // gather batch depth (8 x float4 = 32 regs)

// ---------------- global scratch (zero state; kernel self-restores) ------
__device__ int          g_cnt[C_CORES];            // per-core counts
__device__ unsigned int g_tab[CD];                 // encoded segmax table
__device__ int gb2a, gb2d, gb3a, gb3d;             // barrier counters

__device__ __forceinline__ unsigned int enc(float f) {
    unsigned int u = __float_as_uint(f);
    return (u & 0x80000000u) ? ~u : (u | 0x80000000u);
}
__device__ __forceinline__ float dec(unsigned int u) {
    u = (u & 0x80000000u) ? (u & 0x7fffffffu) : ~u;
    return __uint_as_float(u);
}
__device__ __forceinline__ float neg_inf() { return __int_as_float(0xff800000); }

#define FMAX4(d, v) { d.x = fmaxf(d.x, (v).x); d.y = fmaxf(d.y, (v).y); \
                      d.z = fmaxf(d.z, (v).z); d.w = fmaxf(d.w, (v).w); }

__global__ __launch_bounds__(TPB, 1)
void fused(const int*   __restrict__ assign,
           const float* __restrict__ emb,
           const float* __restrict__ padding_emb,
           const float* __restrict__ core_con,
           const float* __restrict__ W_self,
           const float* __restrict__ W_msg,
           const float* __restrict__ bvec,
           float*       __restrict__ out,
           int Q)
{
    extern __shared__ char smraw[];
    const int tid  = threadIdx.x;
    const int wid  = tid >> 5;
    const int lane = tid & 31;
    const int grid = gridDim.x;

    const float4* e4 = (const float4*)emb;

    // ============ phase 1a: bin this block's slice into smem lists ========
    {
        int* s_cnt = (int*)smraw;              // 64
        int* s_bin = s_cnt + C_CORES;          // 64 * CAP

        if (tid < C_CORES) s_cnt[tid] = 0;
        __syncthreads();

        const int chunk = (Q + grid - 1) / grid;
        const int qa0 = blockIdx.x * chunk;
        const int qa1 = min(qa0 + chunk, Q);

        for (int i = qa0 + tid; i < qa1; i += TPB) {
            int c = __ldg(assign + i);
            int idx = atomicAdd(&s_cnt[c], 1);
            if (idx < CAP) {
                s_bin[c * CAP + idx] = i;
            } else {
                // cold overflow path (prob ~0): fold the row directly
                const float4* row = e4 + (size_t)i * 32;
                for (int j = 0; j < 32; j++) {
                    float4 v = __ldg(row + j);
                    unsigned int* gp = g_tab + c * D_EMB + j * 4;
                    atomicMax(gp + 0, enc(v.x));
                    atomicMax(gp + 1, enc(v.y));
                    atomicMax(gp + 2, enc(v.z));
                    atomicMax(gp + 3, enc(v.w));
                }
            }
        }
        __syncthreads();

        if (tid < C_CORES && s_cnt[tid] > 0)
            atomicAdd(&g_cnt[tid], s_cnt[tid]);

        // ============ phase 1b: register gather-max, 4 cores per warp =====
#pragma unroll
        for (int g = 0; g < CPW; g++) {
            const int core = wid * CPW + g;
            const int n = min(s_cnt[core], CAP);
            const int* list = s_bin + core * CAP;

            float4 acc = make_float4(neg_inf(), neg_inf(), neg_inf(), neg_inf());

            for (int i = 0; i < n; i += BD) {
                const int m = min(BD, n - i);
                int    q[BD];
                float4 v[BD];
#pragma unroll
                for (int u = 0; u < BD; u++)
                    if (u < m) q[u] = list[i + u];        // LDS broadcast
#pragma unroll
                for (int u = 0; u < BD; u++)
                    if (u < m) v[u] = __ldg(e4 + (size_t)q[u] * 32 + lane); // LDG.128
#pragma unroll
                for (int u = 0; u < BD; u++)
                    if (u < m) FMAX4(acc, v[u]);
            }
            if (n > 0) {
                unsigned int* gp = g_tab + core * D_EMB + lane * 4;
                atomicMax(gp + 0, enc(acc.x));
                atomicMax(gp + 1, enc(acc.y));
                atomicMax(gp + 2, enc(acc.z));
                atomicMax(gp + 3, enc(acc.w));
            }
        }
    }

    // ================= grid barrier (blocks >= 64 exit) ====================
    __threadfence();
    __syncthreads();
    if (blockIdx.x >= C_CORES) {
        if (tid == 0) atomicAdd(&gb2a, 1);
        return;
    }
    if (tid == 0) {
        atomicAdd(&gb2a, 1);
        while (atomicAdd(&gb2a, 0) < grid) __nanosleep(32);
        if (atomicAdd(&gb2d, 1) == C_CORES - 1) {
            atomicExch(&gb2a, 0);
            atomicExch(&gb2d, 0);
        }
        __threadfence();
    }
    __syncthreads();

    // ================= epilogue: decode E + fused GNN =====================
    float (*sE)[D_EMB] = (float(*)[D_EMB])smraw;          // 32 KB (reuse)
    float* sMp = (float*)smraw + CD;                      // 4 x 128
    float* sM  = sMp + 4 * D_EMB;                         // 128
    float* sO  = sM + D_EMB;                              // 4 x 128

    const int c = blockIdx.x;
    const int t = tid & 127;
    const int s = tid >> 7;                               // 0..3

    {
        const float pad = __ldg(&padding_emb[t]);
#pragma unroll
        for (int j = s * 16; j < s * 16 + 16; j++) {
            int cnt = __ldcg(&g_cnt[j]);
            unsigned int u = __ldcg(&g_tab[j * D_EMB + t]);
            sE[j][t] = (cnt > 0) ? dec(u) : pad;
        }
    }
    __syncthreads();

    // ---- barrier among the 64 epilogue blocks (all reads done) -----------
    if (tid == 0) {
        atomicAdd(&gb3a, 1);
        while (atomicAdd(&gb3a, 0) < C_CORES) __nanosleep(32);
        if (atomicAdd(&gb3d, 1) == C_CORES - 1) {
            atomicExch(&gb3a, 0);
            atomicExch(&gb3d, 0);
        }
        __threadfence();
    }
    __syncthreads();

    // restore zero state for next graph replay
    if (tid < 32) ((uint4*)g_tab)[c * 32 + tid] = make_uint4(0, 0, 0, 0);
    if (c == 0 && tid >= 32 && tid < 32 + C_CORES) g_cnt[tid - 32] = 0;

    // Msum[t] = sum_j con[c,j] * E[j,t]   (4-way split)
    {
        float a = 0.f;
#pragma unroll
        for (int j = s * 16; j < s * 16 + 16; j++)
            a = fmaf(__ldg(&core_con[c * C_CORES + j]), sE[j][t], a);
        sMp[s * D_EMB + t] = a;
    }
    __syncthreads();
    if (s == 0) {
        float m = 0.f;
#pragma unroll
        for (int r = 0; r < 4; r++) m += sMp[r * D_EMB + t];
        sM[t] = m;
    }
    __syncthreads();

    // out = relu(E@W_self + Msum@W_msg + b)   (4-way K split)
    {
        float a0 = 0.f, a1 = 0.f;
#pragma unroll
        for (int kk = s * 32; kk < s * 32 + 32; kk++) {
            a0 = fmaf(sE[c][kk], __ldg(&W_self[kk * D_EMB + t]), a0);
            a1 = fmaf(sM[kk],    __ldg(&W_msg [kk * D_EMB + t]), a1);
        }
        sO[s * D_EMB + t] = a0 + a1;
    }
    __syncthreads();
    if (s == 0) {
        float r = __ldg(&bvec[t]);
#pragma unroll
        for (int q = 0; q < 4; q++) r += sO[q * D_EMB + t];
        out[c * D_EMB + t] = fmaxf(r, 0.f);
    }
}

// ---------------- launch ----------------
extern "C" void kernel_launch(void* const* d_in, const int* in_sizes, int n_in,
                              void* d_out, int out_size)
{
    const int*   assign      = (const int*)  d_in[0];
    const float* emb         = (const float*)d_in[1];
    const float* padding_emb = (const float*)d_in[2];
    const float* core_con    = (const float*)d_in[3];
    const float* W_self      = (const float*)d_in[4];
    const float* W_msg       = (const float*)d_in[5];
    const float* bvec        = (const float*)d_in[6];
    float* out = (float*)d_out;

    const int Q = in_sizes[0];

    int nsm = 148;
    cudaDeviceGetAttribute(&nsm, cudaDevAttrMultiProcessorCount, 0);
    if (nsm < C_CORES) nsm = C_CORES;

    // smem: max(phase1: (64 + 64*CAP)*4 = 65.8 KB, epilogue: 37.4 KB)
    int smem1 = (C_CORES + C_CORES * CAP) * (int)sizeof(int);
    int smem2 = (CD + 9 * D_EMB) * (int)sizeof(float);
    int smem  = (smem1 > smem2 ? smem1 : smem2);

    cudaFuncSetAttribute(fused, cudaFuncAttributeMaxDynamicSharedMemorySize, smem);
    fused<<<nsm, TPB, smem>>>(assign, emb, padding_emb, core_con,
                              W_self, W_msg, bvec, out, Q);
}

// round 13
// speedup vs baseline: 1.2449x; 1.2449x over previous
#include <cuda_runtime.h>
#include <cstdint>

// ---------------- problem constants ----------------
#define C_CORES 64
#define D_EMB   128
#define CD      (C_CORES * D_EMB)      // 8192
#define TPB     1024                   // 32 warps: warp w owns cores 2w, 2w+1
#define CAP     256                    // per-core local bin capacity (mean ~21)

// ---------------- global scratch (zero state; kernel self-restores) ------
__device__ int          g_cnt[C_CORES];            // per-core counts
__device__ unsigned int g_tab[CD];                 // encoded segmax table
__device__ int gb2a, gb2d, gb3a, gb3d;             // barrier counters

__device__ __forceinline__ unsigned int enc(float f) {
    unsigned int u = __float_as_uint(f);
    return (u & 0x80000000u) ? ~u : (u | 0x80000000u);
}
__device__ __forceinline__ float dec(unsigned int u) {
    u = (u & 0x80000000u) ? (u & 0x7fffffffu) : ~u;
    return __uint_as_float(u);
}
__device__ __forceinline__ float neg_inf() { return __int_as_float(0xff800000); }

#define FMAX4(d, v) { d.x = fmaxf(d.x, (v).x); d.y = fmaxf(d.y, (v).y); \
                      d.z = fmaxf(d.z, (v).z); d.w = fmaxf(d.w, (v).w); }

__global__ __launch_bounds__(TPB, 1)
void fused(const int*   __restrict__ assign,
           const float* __restrict__ emb,
           const float* __restrict__ padding_emb,
           const float* __restrict__ core_con,
           const float* __restrict__ W_self,
           const float* __restrict__ W_msg,
           const float* __restrict__ bvec,
           float*       __restrict__ out,
           int Q)
{
    extern __shared__ char smraw[];
    const int tid  = threadIdx.x;
    const int wid  = tid >> 5;
    const int lane = tid & 31;
    const int grid = gridDim.x;

    const float4* e4 = (const float4*)emb;

    // ============ phase 1a: bin this block's slice into smem lists ========
    {
        int* s_cnt = (int*)smraw;              // 64
        int* s_bin = s_cnt + C_CORES;          // 64 * CAP

        if (tid < C_CORES) s_cnt[tid] = 0;
        __syncthreads();

        const int chunk = (Q + grid - 1) / grid;
        const int qa0 = blockIdx.x * chunk;
        const int qa1 = min(qa0 + chunk, Q);

        for (int i = qa0 + tid; i < qa1; i += TPB) {
            int c = __ldg(assign + i);
            int idx = atomicAdd(&s_cnt[c], 1);
            if (idx < CAP) {
                s_bin[c * CAP + idx] = i;
            } else {
                // cold overflow path (prob ~0): fold the row directly
                const float4* row = e4 + (size_t)i * 32;
                for (int j = 0; j < 32; j++) {
                    float4 v = __ldg(row + j);
                    unsigned int* gp = g_tab + c * D_EMB + j * 4;
                    atomicMax(gp + 0, enc(v.x));
                    atomicMax(gp + 1, enc(v.y));
                    atomicMax(gp + 2, enc(v.z));
                    atomicMax(gp + 3, enc(v.w));
                }
            }
        }
        __syncthreads();

        if (tid < C_CORES && s_cnt[tid] > 0)
            atomicAdd(&g_cnt[tid], s_cnt[tid]);

        // ===== phase 1b: dual-stream clamped gather-max (branch-free) =====
        {
            const int coreA = wid * 2;
            const int coreB = wid * 2 + 1;
            const int origA = min(s_cnt[coreA], CAP);
            const int origB = min(s_cnt[coreB], CAP);
            const int* listA = s_bin + coreA * CAP;
            const int* listB = s_bin + coreB * CAP;
            int nA = origA, nB = origB;

            // redirect empty stream to the sibling (dup work; result discarded)
            if (nA == 0) { listA = listB; nA = nB; }
            if (nB == 0) { listB = listA; nB = nA; }

            if (nA > 0) {
                float4 accA = make_float4(neg_inf(), neg_inf(), neg_inf(), neg_inf());
                float4 accB = accA;
                const int nmax = max(nA, nB);
                const int lA = nA - 1, lB = nB - 1;

                for (int i = 0; i < nmax; i += 2) {
                    // clamped indices: duplicates are no-ops under max
                    int ia0 = min(i,     lA);
                    int ia1 = min(i + 1, lA);
                    int ib0 = min(i,     lB);
                    int ib1 = min(i + 1, lB);
                    int qa0 = listA[ia0];
                    int qa1 = listA[ia1];
                    int qb0 = listB[ib0];
                    int qb1 = listB[ib1];
                    // 4 unconditional independent LDG.128 -> 2 KB in flight
                    float4 va0 = __ldg(e4 + (size_t)qa0 * 32 + lane);
                    float4 va1 = __ldg(e4 + (size_t)qa1 * 32 + lane);
                    float4 vb0 = __ldg(e4 + (size_t)qb0 * 32 + lane);
                    float4 vb1 = __ldg(e4 + (size_t)qb1 * 32 + lane);
                    FMAX4(accA, va0);
                    FMAX4(accA, va1);
                    FMAX4(accB, vb0);
                    FMAX4(accB, vb1);
                }

                if (origA > 0) {
                    unsigned int* gp = g_tab + coreA * D_EMB + lane * 4;
                    atomicMax(gp + 0, enc(accA.x));
                    atomicMax(gp + 1, enc(accA.y));
                    atomicMax(gp + 2, enc(accA.z));
                    atomicMax(gp + 3, enc(accA.w));
                }
                if (origB > 0) {
                    unsigned int* gp = g_tab + coreB * D_EMB + lane * 4;
                    atomicMax(gp + 0, enc(accB.x));
                    atomicMax(gp + 1, enc(accB.y));
                    atomicMax(gp + 2, enc(accB.z));
                    atomicMax(gp + 3, enc(accB.w));
                }
            }
        }
    }

    // ================= grid barrier (blocks >= 64 exit) ====================
    __threadfence();
    __syncthreads();
    if (blockIdx.x >= C_CORES) {
        if (tid == 0) atomicAdd(&gb2a, 1);
        return;
    }
    if (tid == 0) {
        atomicAdd(&gb2a, 1);
        while (atomicAdd(&gb2a, 0) < grid) __nanosleep(32);
        if (atomicAdd(&gb2d, 1) == C_CORES - 1) {
            atomicExch(&gb2a, 0);
            atomicExch(&gb2d, 0);
        }
        __threadfence();
    }
    __syncthreads();

    // ================= epilogue: decode E + fused GNN =====================
    float (*sE)[D_EMB] = (float(*)[D_EMB])smraw;          // 32 KB (reuse)
    float* sMp = (float*)smraw + CD;                      // 8 x 128
    float* sM  = sMp + 8 * D_EMB;                         // 128
    float* sO  = sM + D_EMB;                              // 8 x 128

    const int c = blockIdx.x;
    const int t = tid & 127;
    const int s = tid >> 7;                               // 0..7

    {
        const float pad = __ldg(&padding_emb[t]);
#pragma unroll
        for (int j = s * 8; j < s * 8 + 8; j++) {
            int cnt = __ldcg(&g_cnt[j]);
            unsigned int u = __ldcg(&g_tab[j * D_EMB + t]);
            sE[j][t] = (cnt > 0) ? dec(u) : pad;
        }
    }
    __syncthreads();

    // ---- barrier among the 64 epilogue blocks (all reads done) -----------
    if (tid == 0) {
        atomicAdd(&gb3a, 1);
        while (atomicAdd(&gb3a, 0) < C_CORES) __nanosleep(32);
        if (atomicAdd(&gb3d, 1) == C_CORES - 1) {
            atomicExch(&gb3a, 0);
            atomicExch(&gb3d, 0);
        }
        __threadfence();
    }
    __syncthreads();

    // restore zero state for next graph replay
    if (tid < 32) ((uint4*)g_tab)[c * 32 + tid] = make_uint4(0, 0, 0, 0);
    if (c == 0 && tid >= 32 && tid < 32 + C_CORES) g_cnt[tid - 32] = 0;

    // Msum[t] = sum_j con[c,j] * E[j,t]   (8-way split)
    {
        float a = 0.f;
#pragma unroll
        for (int j = s * 8; j < s * 8 + 8; j++)
            a = fmaf(__ldg(&core_con[c * C_CORES + j]), sE[j][t], a);
        sMp[s * D_EMB + t] = a;
    }
    __syncthreads();
    if (s == 0) {
        float m = 0.f;
#pragma unroll
        for (int r = 0; r < 8; r++) m += sMp[r * D_EMB + t];
        sM[t] = m;
    }
    __syncthreads();

    // out = relu(E@W_self + Msum@W_msg + b)   (8-way K split)
    {
        float a0 = 0.f, a1 = 0.f;
#pragma unroll
        for (int kk = s * 16; kk < s * 16 + 16; kk++) {
            a0 = fmaf(sE[c][kk], __ldg(&W_self[kk * D_EMB + t]), a0);
            a1 = fmaf(sM[kk],    __ldg(&W_msg [kk * D_EMB + t]), a1);
        }
        sO[s * D_EMB + t] = a0 + a1;
    }
    __syncthreads();
    if (s == 0) {
        float r = __ldg(&bvec[t]);
#pragma unroll
        for (int q = 0; q < 8; q++) r += sO[q * D_EMB + t];
        out[c * D_EMB + t] = fmaxf(r, 0.f);
    }
}

// ---------------- launch ----------------
extern "C" void kernel_launch(void* const* d_in, const int* in_sizes, int n_in,
                              void* d_out, int out_size)
{
    const int*   assign      = (const int*)  d_in[0];
    const float* emb         = (const float*)d_in[1];
    const float* padding_emb = (const float*)d_in[2];
    const float* core_con    = (const float*)d_in[3];
    const float* W_self      = (const float*)d_in[4];
    const float* W_msg       = (const float*)d_in[5];
    const float* bvec        = (const float*)d_in[6];
    float* out = (float*)d_out;

    const int Q = in_sizes[0];

    int nsm = 148;
    cudaDeviceGetAttribute(&nsm, cudaDevAttrMultiProcessorCount, 0);
    if (nsm < C_CORES) nsm = C_CORES;

    // smem: max(phase1: (64 + 64*CAP)*4 = 65.8 KB, epilogue: 41.5 KB)
    int smem1 = (C_CORES + C_CORES * CAP) * (int)sizeof(int);
    int smem2 = (CD + 17 * D_EMB) * (int)sizeof(float);
    int smem  = (smem1 > smem2 ? smem1 : smem2);

    cudaFuncSetAttribute(fused, cudaFuncAttributeMaxDynamicSharedMemorySize, smem);
    fused<<<nsm, TPB, smem>>>(assign, emb, padding_emb, core_con,
                              W_self, W_msg, bvec, out, Q);
}

// round 14
// speedup vs baseline: 1.4090x; 1.1319x over previous
#include <cuda_runtime.h>
#include <cstdint>

// ---------------- problem constants ----------------
#define C_CORES 64
#define D_EMB   128
#define CD      (C_CORES * D_EMB)      // 8192
#define TPB     1024                   // 32 warps: warp w owns cores 2w, 2w+1
#define CAP     256                    // per-core local bin capacity (mean ~21)

// ---------------- global scratch (zero state; kernel self-restores) ------
__device__ int          g_cnt[C_CORES];            // per-core counts
__device__ unsigned int g_tab[CD];                 // encoded segmax table
__device__ int gb2a, gb2d, gb3a, gb3d;             // barrier counters

__device__ __forceinline__ unsigned int enc(float f) {
    unsigned int u = __float_as_uint(f);
    return (u & 0x80000000u) ? ~u : (u | 0x80000000u);
}
__device__ __forceinline__ float dec(unsigned int u) {
    u = (u & 0x80000000u) ? (u & 0x7fffffffu) : ~u;
    return __uint_as_float(u);
}
__device__ __forceinline__ float neg_inf() { return __int_as_float(0xff800000); }

#define FMAX4(d, v) { d.x = fmaxf(d.x, (v).x); d.y = fmaxf(d.y, (v).y); \
                      d.z = fmaxf(d.z, (v).z); d.w = fmaxf(d.w, (v).w); }

__global__ __launch_bounds__(TPB, 1)
void fused(const int*   __restrict__ assign,
           const float* __restrict__ emb,
           const float* __restrict__ padding_emb,
           const float* __restrict__ core_con,
           const float* __restrict__ W_self,
           const float* __restrict__ W_msg,
           const float* __restrict__ bvec,
           float*       __restrict__ out,
           int Q)
{
    extern __shared__ char smraw[];
    const int tid  = threadIdx.x;
    const int wid  = tid >> 5;
    const int lane = tid & 31;
    const int grid = gridDim.x;

    const float4* e4 = (const float4*)emb;

    // ============ phase 1a: bin this block's slice into smem lists ========
    {
        int* s_cnt = (int*)smraw;              // 64
        int* s_bin = s_cnt + C_CORES;          // 64 * CAP

        if (tid < C_CORES) s_cnt[tid] = 0;
        __syncthreads();

        const int chunk = (Q + grid - 1) / grid;
        const int qa0 = blockIdx.x * chunk;
        const int qa1 = min(qa0 + chunk, Q);

        for (int i = qa0 + tid; i < qa1; i += TPB) {
            int c = __ldg(assign + i);
            int idx = atomicAdd(&s_cnt[c], 1);
            if (idx < CAP) {
                s_bin[c * CAP + idx] = i;
            } else {
                // cold overflow path (prob ~0): fold the row directly
                const float4* row = e4 + (size_t)i * 32;
                for (int j = 0; j < 32; j++) {
                    float4 v = __ldg(row + j);
                    unsigned int* gp = g_tab + c * D_EMB + j * 4;
                    atomicMax(gp + 0, enc(v.x));
                    atomicMax(gp + 1, enc(v.y));
                    atomicMax(gp + 2, enc(v.z));
                    atomicMax(gp + 3, enc(v.w));
                }
            }
        }
        __syncthreads();

        if (tid < C_CORES && s_cnt[tid] > 0)
            atomicAdd(&g_cnt[tid], s_cnt[tid]);

        // ===== phase 1b: shfl-indexed clamped gather-max (R10-style body) ==
#pragma unroll
        for (int g = 0; g < 2; g++) {
            const int core = wid * 2 + g;
            const int n = min(s_cnt[core], CAP);
            if (n > 0) {
                const int* list = s_bin + core * CAP;
                const int nlast = n - 1;
                const int nb = (n + 7) >> 3;      // 8-row batches (tail clamped)

                float4 acc = make_float4(neg_inf(), neg_inf(), neg_inf(), neg_inf());

                for (int b = 0; b < nb; b++) {
                    // one coalesced clamped LDS supplies 8 ids via shfl:
                    // lane u holds list[min(b*8+u, n-1)] for u < 8
                    int q32 = list[min(b * 8 + lane, nlast)];
                    float4 v[8];
#pragma unroll
                    for (int u = 0; u < 8; u++) {
                        int q = __shfl_sync(0xffffffffu, q32, u);
                        v[u] = __ldg(e4 + (size_t)q * 32 + lane);  // LDG.128
                    }
#pragma unroll
                    for (int u = 0; u < 8; u++) FMAX4(acc, v[u]);  // dups: no-op
                }

                unsigned int* gp = g_tab + core * D_EMB + lane * 4;
                atomicMax(gp + 0, enc(acc.x));
                atomicMax(gp + 1, enc(acc.y));
                atomicMax(gp + 2, enc(acc.z));
                atomicMax(gp + 3, enc(acc.w));
            }
        }
    }

    // ================= grid barrier (blocks >= 64 exit) ====================
    __threadfence();
    __syncthreads();
    if (blockIdx.x >= C_CORES) {
        if (tid == 0) atomicAdd(&gb2a, 1);
        return;
    }
    if (tid == 0) {
        atomicAdd(&gb2a, 1);
        while (atomicAdd(&gb2a, 0) < grid) __nanosleep(32);
        if (atomicAdd(&gb2d, 1) == C_CORES - 1) {
            atomicExch(&gb2a, 0);
            atomicExch(&gb2d, 0);
        }
        __threadfence();
    }
    __syncthreads();

    // ================= epilogue: decode E + fused GNN =====================
    float (*sE)[D_EMB] = (float(*)[D_EMB])smraw;          // 32 KB (reuse)
    float* sMp = (float*)smraw + CD;                      // 8 x 128
    float* sM  = sMp + 8 * D_EMB;                         // 128
    float* sO  = sM + D_EMB;                              // 8 x 128

    const int c = blockIdx.x;
    const int t = tid & 127;
    const int s = tid >> 7;                               // 0..7

    {
        const float pad = __ldg(&padding_emb[t]);
#pragma unroll
        for (int j = s * 8; j < s * 8 + 8; j++) {
            int cnt = __ldcg(&g_cnt[j]);
            unsigned int u = __ldcg(&g_tab[j * D_EMB + t]);
            sE[j][t] = (cnt > 0) ? dec(u) : pad;
        }
    }
    __syncthreads();

    // ---- barrier among the 64 epilogue blocks (all reads done) -----------
    if (tid == 0) {
        atomicAdd(&gb3a, 1);
        while (atomicAdd(&gb3a, 0) < C_CORES) __nanosleep(32);
        if (atomicAdd(&gb3d, 1) == C_CORES - 1) {
            atomicExch(&gb3a, 0);
            atomicExch(&gb3d, 0);
        }
        __threadfence();
    }
    __syncthreads();

    // restore zero state for next graph replay
    if (tid < 32) ((uint4*)g_tab)[c * 32 + tid] = make_uint4(0, 0, 0, 0);
    if (c == 0 && tid >= 32 && tid < 32 + C_CORES) g_cnt[tid - 32] = 0;

    // Msum[t] = sum_j con[c,j] * E[j,t]   (8-way split)
    {
        float a = 0.f;
#pragma unroll
        for (int j = s * 8; j < s * 8 + 8; j++)
            a = fmaf(__ldg(&core_con[c * C_CORES + j]), sE[j][t], a);
        sMp[s * D_EMB + t] = a;
    }
    __syncthreads();
    if (s == 0) {
        float m = 0.f;
#pragma unroll
        for (int r = 0; r < 8; r++) m += sMp[r * D_EMB + t];
        sM[t] = m;
    }
    __syncthreads();

    // out = relu(E@W_self + Msum@W_msg + b)   (8-way K split)
    {
        float a0 = 0.f, a1 = 0.f;
#pragma unroll
        for (int kk = s * 16; kk < s * 16 + 16; kk++) {
            a0 = fmaf(sE[c][kk], __ldg(&W_self[kk * D_EMB + t]), a0);
            a1 = fmaf(sM[kk],    __ldg(&W_msg [kk * D_EMB + t]), a1);
        }
        sO[s * D_EMB + t] = a0 + a1;
    }
    __syncthreads();
    if (s == 0) {
        float r = __ldg(&bvec[t]);
#pragma unroll
        for (int q = 0; q < 8; q++) r += sO[q * D_EMB + t];
        out[c * D_EMB + t] = fmaxf(r, 0.f);
    }
}

// ---------------- launch ----------------
extern "C" void kernel_launch(void* const* d_in, const int* in_sizes, int n_in,
                              void* d_out, int out_size)
{
    const int*   assign      = (const int*)  d_in[0];
    const float* emb         = (const float*)d_in[1];
    const float* padding_emb = (const float*)d_in[2];
    const float* core_con    = (const float*)d_in[3];
    const float* W_self      = (const float*)d_in[4];
    const float* W_msg       = (const float*)d_in[5];
    const float* bvec        = (const float*)d_in[6];
    float* out = (float*)d_out;

    const int Q = in_sizes[0];

    int nsm = 148;
    cudaDeviceGetAttribute(&nsm, cudaDevAttrMultiProcessorCount, 0);
    if (nsm < C_CORES) nsm = C_CORES;

    // smem: max(phase1: (64 + 64*CAP)*4 = 65.8 KB, epilogue: 41.5 KB)
    int smem1 = (C_CORES + C_CORES * CAP) * (int)sizeof(int);
    int smem2 = (CD + 17 * D_EMB) * (int)sizeof(float);
    int smem  = (smem1 > smem2 ? smem1 : smem2);

    cudaFuncSetAttribute(fused, cudaFuncAttributeMaxDynamicSharedMemorySize, smem);
    fused<<<nsm, TPB, smem>>>(assign, emb, padding_emb, core_con,
                              W_self, W_msg, bvec, out, Q);
}